// round 9
// baseline (speedup 1.0000x reference)
#include <cuda_runtime.h>
#include <cstdint>

// Problem constants (fixed by reference setup_inputs)
#define C_CLS 256
#define S_SUP 5
#define Q_QRY 64
#define DIN   1024
#define ZD    128
#define CS    (C_CLS*S_SUP)              // 1280
#define CQ    (C_CLS*Q_QRY)              // 16384
#define M_TOT (CS+CQ)                    // 17664
#define NPAIRS (C_CLS*(Q_QRY*(Q_QRY-1)/2)) // 516096
#define EPSF  1e-8f
#define NSTG  32                          // k_gemm: K stages of 32
#define DLSTG 8                           // k_dloo: K stages of 16

// k_gemm smem geometry (floats): A = 2 half-stages of [2 kc x 1040], B raw
#define GA_H  1040                        // per-kc (8-k) stride, bank-padded
#define GA_Q  2080                        // per-16k group stride
#define G_BB  4160                        // B base
#define G_BUF 8256                        // per-buffer floats (A 4160 + B 4096)
// k_dloo smem geometry
#define D_BB  2080
#define D_BUF 6176                        // A 2080 + B 4096

// ---------------- device scratch (no allocations allowed) ----------------
__device__ __align__(16) float g_z[(size_t)M_TOT * ZD];        // ~9 MB
__device__ __align__(16) float g_proto2[C_CLS];                // ||proto_c||^2
__device__ __align__(16) float g_row2[M_TOT];                  // ||z_row||^2
// RAW W, pos-permuted image: [k8_idx(128)][n(128)][8 pos]
__device__ __align__(16) float g_Wp[128 * 1024];               // 512 KB
// RAW protoT, pos-permuted image: [k8(16)][n(256)][8 pos]
__device__ __align__(16) float g_Pp[16 * 2048];                // 128 KB
__device__ float g_cos_sum;
__device__ float g_acc_cnt;

// ---------------- helpers ----------------
__device__ __forceinline__ uint32_t smem_u32(const void* p){
    uint32_t a; asm("{ .reg .u64 t; cvta.to.shared.u64 t, %1; cvt.u32.u64 %0, t; }"
                    : "=r"(a) : "l"(p));
    return a;
}
__device__ __forceinline__ float tf32_rna(float a){
    uint32_t r; asm("cvt.rna.tf32.f32 %0, %1;" : "=r"(r) : "f"(a));
    return __uint_as_float(r);
}
__device__ __forceinline__ void cp16(uint32_t saddr, const void* g){
    asm volatile("cp.async.cg.shared.global [%0], [%1], 16;" :: "r"(saddr), "l"(g));
}
#define CP_COMMIT() asm volatile("cp.async.commit_group;" ::: "memory")
#define CP_WAIT0()  asm volatile("cp.async.wait_group 0;"  ::: "memory")

// D += A(16x8,row) * B(8x8,col)   tf32 inputs, fp32 accum (validated R5-R8)
__device__ __forceinline__ void mma8(float4 &d, float2 a01, float2 a23, float2 b){
    asm volatile("mma.sync.aligned.m16n8k8.row.col.f32.tf32.tf32.f32 "
        "{%0,%1,%2,%3}, {%4,%5,%6,%7}, {%8,%9}, {%0,%1,%2,%3};"
        : "+f"(d.x), "+f"(d.y), "+f"(d.z), "+f"(d.w)
        : "r"(__float_as_uint(a01.x)), "r"(__float_as_uint(a23.x)),
          "r"(__float_as_uint(a01.y)), "r"(__float_as_uint(a23.y)),
          "r"(__float_as_uint(b.x)),   "r"(__float_as_uint(b.y)));
}
// split raw float2 into tf32 hi + residual lo (in registers)
__device__ __forceinline__ void split2(float2 raw, float2 &hi, float2 &lo){
    hi.x = tf32_rna(raw.x); hi.y = tf32_rna(raw.y);
    lo.x = raw.x - hi.x;    lo.y = raw.y - hi.y;
}

// =====================================================================
// KW: permute W[k=1024][n=128] into RAW pos-order image, row order
// [k0,k4,k1,k5,k2,k6,k3,k7] per k8-chunk (validated layout).
// =====================================================================
__global__ __launch_bounds__(256) void k_wperm(const float* __restrict__ W){
    const int s   = blockIdx.x;          // 0..31 (4 k8-chunks each)
    const int t   = threadIdx.x;
    const int n   = t >> 1;
    const int h   = t & 1;
#pragma unroll
    for (int kc = 0; kc < 4; kc++){
        const int kb = s * 32 + kc * 8 + 2 * h;
        const float v0 = W[(size_t)(kb + 0) * ZD + n];
        const float v1 = W[(size_t)(kb + 1) * ZD + n];
        const float v4 = W[(size_t)(kb + 4) * ZD + n];
        const float v5 = W[(size_t)(kb + 5) * ZD + n];
        const int off = (s * 4 + kc) * 1024 + n * 8 + h * 4;
        *(float4*)&g_Wp[off] = make_float4(v0, v4, v1, v5);
    }
}

// =====================================================================
// K1: z = [xs; xq] @ W, mma.sync tf32 3-pass, hi/lo in registers,
// PASS-MAJOR mma order (dependent-chain distance 8). 512 threads =
// 16 warps (4m x 4n), warp tile 32x32, BK=32, 32 stages double-buffered.
// B via cp.async from g_Wp. Epilogue: z + fused ||row||^2.
// =====================================================================
__global__ __launch_bounds__(512) void k_gemm(const float* __restrict__ xs,
                                              const float* __restrict__ xq){
    extern __shared__ float sb[];        // 2 x G_BUF floats (~66 KB)
    __shared__ float s_r2[128];

    const int tid  = threadIdx.x;
    const int lane = tid & 31;
    const int wid  = tid >> 5;
    const int g    = lane >> 2;
    const int tg   = lane & 3;
    const int m0   = (wid & 3) * 32;
    const int n0   = (wid >> 2) * 32;
    const int bm   = blockIdx.x;
    const float* X = (bm < 10) ? (xs + (size_t)bm * (128 * DIN))
                               : (xq + (size_t)(bm - 10) * (128 * DIN));
    const int sm_m = tid >> 2;
    const int skc  = (tid >> 1) & 1;
    const int sh   = tid & 1;
    const int sts_off = skc * GA_H + sm_m * 8 + sh * 4;   // conflict-free (R8-verified)

    float4 acc[2][4];
#pragma unroll
    for (int i = 0; i < 2; i++)
#pragma unroll
        for (int j = 0; j < 4; j++) acc[i][j] = make_float4(0.f, 0.f, 0.f, 0.f);

    float4 rA[2];
    // prologue: stage 0 (32 k)
    {
        float* buf = sb;
        const uint32_t bb = smem_u32(&buf[G_BB]);
        cp16(bb + tid * 32,      g_Wp + tid * 8);
        cp16(bb + tid * 32 + 16, g_Wp + tid * 8 + 4);
        CP_COMMIT();
#pragma unroll
        for (int kq = 0; kq < 2; kq++){
            const float* xp = X + (size_t)sm_m * DIN + kq * 16 + skc * 8 + sh * 2;
            const float2 fa = *(const float2*)xp;
            const float2 fb = *(const float2*)(xp + 4);
            rA[kq] = make_float4(fa.x, fb.x, fa.y, fb.y);
            *(float4*)&buf[kq * GA_Q + sts_off] = rA[kq];
        }
        CP_WAIT0();
    }
    __syncthreads();

    for (int s = 0; s < NSTG; s++){
        const int b = s & 1;
        const float* buf = sb + b * G_BUF;
        float* nbuf = sb + (b ^ 1) * G_BUF;
        if (s + 1 < NSTG){
            const uint32_t bb = smem_u32(&nbuf[G_BB]);
            const float* src = g_Wp + (s + 1) * 4096;
            cp16(bb + tid * 32,      src + tid * 8);
            cp16(bb + tid * 32 + 16, src + tid * 8 + 4);
            CP_COMMIT();
#pragma unroll
            for (int kq = 0; kq < 2; kq++){
                const float* xp = X + (size_t)sm_m * DIN + (s + 1) * 32 + kq * 16 + skc * 8 + sh * 2;
                const float2 fa = *(const float2*)xp;
                const float2 fb = *(const float2*)(xp + 4);
                rA[kq] = make_float4(fa.x, fb.x, fa.y, fb.y);
            }
        }
#pragma unroll
        for (int kq = 0; kq < 4; kq++){
            const float* Ar = buf + (kq >> 1) * GA_Q + (kq & 1) * GA_H;
            const float* Br = buf + G_BB + kq * 1024;
            float2 bh[4], bl[4];
#pragma unroll
            for (int j = 0; j < 4; j++){
                const int nr = (n0 + j * 8 + g) * 8 + 2 * tg;
                split2(*(const float2*)&Br[nr], bh[j], bl[j]);
            }
            float2 ah[2][2], al[2][2];
#pragma unroll
            for (int mt = 0; mt < 2; mt++){
                const int r0 = (m0 + mt * 16 + g) * 8 + 2 * tg;
                split2(*(const float2*)&Ar[r0],      ah[mt][0], al[mt][0]);
                split2(*(const float2*)&Ar[r0 + 64], ah[mt][1], al[mt][1]);
            }
            // pass-major: 8 independent accs between dependent uses
#pragma unroll
            for (int mt = 0; mt < 2; mt++)
#pragma unroll
                for (int j = 0; j < 4; j++)
                    mma8(acc[mt][j], ah[mt][0], ah[mt][1], bh[j]);
#pragma unroll
            for (int mt = 0; mt < 2; mt++)
#pragma unroll
                for (int j = 0; j < 4; j++)
                    mma8(acc[mt][j], al[mt][0], al[mt][1], bh[j]);
#pragma unroll
            for (int mt = 0; mt < 2; mt++)
#pragma unroll
                for (int j = 0; j < 4; j++)
                    mma8(acc[mt][j], ah[mt][0], ah[mt][1], bl[j]);
        }
        if (s + 1 < NSTG){
#pragma unroll
            for (int kq = 0; kq < 2; kq++)
                *(float4*)&nbuf[kq * GA_Q + sts_off] = rA[kq];
            CP_WAIT0();
            __syncthreads();
        }
    }

    // ---- epilogue: z store + fused row norms ----
    if (tid < 128) s_r2[tid] = 0.0f;
    __syncthreads();
    const size_t rb = (size_t)bm * 128;
#pragma unroll
    for (int mt = 0; mt < 2; mt++){
        const int r0 = m0 + mt * 16 + g;
        float s0 = 0.0f, s1 = 0.0f;
#pragma unroll
        for (int j = 0; j < 4; j++){
            const float4 a = acc[mt][j];
            const int col = n0 + j * 8 + 2 * tg;
            *(float2*)(g_z + (rb + r0) * ZD + col)     = make_float2(a.x, a.y);
            *(float2*)(g_z + (rb + r0 + 8) * ZD + col) = make_float2(a.z, a.w);
            s0 = fmaf(a.x, a.x, s0); s0 = fmaf(a.y, a.y, s0);
            s1 = fmaf(a.z, a.z, s1); s1 = fmaf(a.w, a.w, s1);
        }
        s0 += __shfl_xor_sync(0xffffffffu, s0, 1);
        s0 += __shfl_xor_sync(0xffffffffu, s0, 2);
        s1 += __shfl_xor_sync(0xffffffffu, s1, 1);
        s1 += __shfl_xor_sync(0xffffffffu, s1, 2);
        if (tg == 0){
            atomicAdd(&s_r2[r0],     s0);
            atomicAdd(&s_r2[r0 + 8], s1);
        }
    }
    __syncthreads();
    if (tid < 128) g_row2[rb + tid] = s_r2[tid];
}

// ---------------- K2: prototypes + ||proto||^2 + raw permuted image -----
__global__ __launch_bounds__(128) void k_proto(){
    const int c = blockIdx.x;
    const int d = threadIdx.x;  // 0..127 (= k index)
    if (c == 0 && d == 0){ g_cos_sum = 0.0f; g_acc_cnt = 0.0f; }
    const float* z = g_z + (size_t)c * S_SUP * ZD + d;
    float p = 0.0f;
#pragma unroll
    for (int s = 0; s < S_SUP; s++) p += z[s * ZD];
    p *= (1.0f / S_SUP);
    const int k8  = d >> 3;
    const int pos = ((d & 3) << 1) | ((d >> 2) & 1);
    g_Pp[k8 * 2048 + c * 8 + pos] = p;
    float sq = p * p;
#pragma unroll
    for (int o = 16; o; o >>= 1) sq += __shfl_xor_sync(0xffffffffu, sq, o);
    __shared__ float w[4];
    if ((d & 31) == 0) w[d >> 5] = sq;
    __syncthreads();
    if (d == 0) g_proto2[c] = w[0] + w[1] + w[2] + w[3];
}

// =====================================================================
// K3 (fused d2 + loo): one CTA per 2 classes. GEMM M=128 x N=256 x K=128,
// 3-pass tf32, PASS-MAJOR, warp tile 64x32 (16 warps: 2m x 8n) so B
// fragments (bh[4]/bl[4]) fit registers and are split ONCE per kc.
// d2 -> SMEM (stride 264) then in-CTA loo-norm + cos identity + argmin.
// =====================================================================
__global__ __launch_bounds__(512) void k_dloo(){
    extern __shared__ float sb[];        // max(2*D_BUF, 128*264) floats
    __shared__ float s_part[16][256];
    __shared__ float s_red[16];
    __shared__ float s_scal[4];          // [sumA2_c0, cnt_c0, sumA2_c1, cnt_c1]

    const int tid  = threadIdx.x;
    const int lane = tid & 31;
    const int wid  = tid >> 5;           // 0..15
    const int g    = lane >> 2;
    const int tg   = lane & 3;
    const int m0   = (wid & 1) * 64;     // 2 m-groups of 64 rows
    const int n0   = (wid >> 1) * 32;    // 8 n-groups of 32 cols
    const int qb   = blockIdx.x;         // class pair
    const float* X = g_z + (size_t)(CS + qb * 128) * ZD;
    const int sm_m = tid >> 2;
    const int skc  = (tid >> 1) & 1;
    const int sh   = tid & 1;
    const int sts_off = skc * GA_H + sm_m * 8 + sh * 4;

    if (tid < 4) s_scal[tid] = 0.0f;

    float4 acc[4][4];
#pragma unroll
    for (int i = 0; i < 4; i++)
#pragma unroll
        for (int j = 0; j < 4; j++) acc[i][j] = make_float4(0.f, 0.f, 0.f, 0.f);

    float4 rA;
    // prologue: stage 0
    {
        float* buf = sb;
        const uint32_t bb = smem_u32(&buf[D_BB]);
        cp16(bb + tid * 32,      g_Pp + tid * 8);
        cp16(bb + tid * 32 + 16, g_Pp + tid * 8 + 4);
        CP_COMMIT();
        const float* xp = X + (size_t)sm_m * ZD + skc * 8 + sh * 2;
        const float2 fa = *(const float2*)xp;
        const float2 fb = *(const float2*)(xp + 4);
        rA = make_float4(fa.x, fb.x, fa.y, fb.y);
        *(float4*)&buf[sts_off] = rA;
        CP_WAIT0();
    }
    __syncthreads();

    for (int s = 0; s < DLSTG; s++){
        const int b = s & 1;
        const float* buf = sb + b * D_BUF;
        float* nbuf = sb + (b ^ 1) * D_BUF;
        if (s + 1 < DLSTG){
            const uint32_t bb = smem_u32(&nbuf[D_BB]);
            const float* src = g_Pp + (s + 1) * 4096;
            cp16(bb + tid * 32,      src + tid * 8);
            cp16(bb + tid * 32 + 16, src + tid * 8 + 4);
            CP_COMMIT();
            const float* xp = X + (size_t)sm_m * ZD + (s + 1) * 16 + skc * 8 + sh * 2;
            const float2 fa = *(const float2*)xp;
            const float2 fb = *(const float2*)(xp + 4);
            rA = make_float4(fa.x, fb.x, fa.y, fb.y);
        }
#pragma unroll
        for (int kc = 0; kc < 2; kc++){
            const float* Ar = buf + kc * GA_H;
            const float* Br = buf + D_BB + kc * 2048;
            float2 bh[4], bl[4];
#pragma unroll
            for (int j = 0; j < 4; j++){
                const int nr = (n0 + j * 8 + g) * 8 + 2 * tg;
                split2(*(const float2*)&Br[nr], bh[j], bl[j]);
            }
            // two mt-pairs, each pass-major over 8 accumulators
#pragma unroll
            for (int mp = 0; mp < 2; mp++){
                float2 ah[2][2], al[2][2];
#pragma unroll
                for (int t2 = 0; t2 < 2; t2++){
                    const int mt = mp * 2 + t2;
                    const int r0 = (m0 + mt * 16 + g) * 8 + 2 * tg;
                    split2(*(const float2*)&Ar[r0],      ah[t2][0], al[t2][0]);
                    split2(*(const float2*)&Ar[r0 + 64], ah[t2][1], al[t2][1]);
                }
#pragma unroll
                for (int t2 = 0; t2 < 2; t2++)
#pragma unroll
                    for (int j = 0; j < 4; j++)
                        mma8(acc[mp * 2 + t2][j], ah[t2][0], ah[t2][1], bh[j]);
#pragma unroll
                for (int t2 = 0; t2 < 2; t2++)
#pragma unroll
                    for (int j = 0; j < 4; j++)
                        mma8(acc[mp * 2 + t2][j], al[t2][0], al[t2][1], bh[j]);
#pragma unroll
                for (int t2 = 0; t2 < 2; t2++)
#pragma unroll
                    for (int j = 0; j < 4; j++)
                        mma8(acc[mp * 2 + t2][j], ah[t2][0], ah[t2][1], bl[j]);
            }
        }
        if (s + 1 < DLSTG){
            *(float4*)&nbuf[sts_off] = rA;
            CP_WAIT0();
            __syncthreads();
        }
    }

    // ---- d2 into SMEM (reuses stage buffers; stride 264) ----
    __syncthreads();                     // all warps done reading buffers
    float* d2s = sb;                     // 128 x 264 floats
#pragma unroll
    for (int mt = 0; mt < 4; mt++){
        const int r = m0 + mt * 16 + g;
        const float qn0 = g_row2[CS + qb * 128 + r];
        const float qn1 = g_row2[CS + qb * 128 + r + 8];
#pragma unroll
        for (int j = 0; j < 4; j++){
            const int col = n0 + j * 8 + 2 * tg;
            const float pn0 = g_proto2[col];
            const float pn1 = g_proto2[col + 1];
            const float4 a = acc[mt][j];
            *(float2*)&d2s[r * 264 + col] =
                make_float2(qn0 + pn0 - 2.0f * a.x, qn0 + pn1 - 2.0f * a.y);
            *(float2*)&d2s[(r + 8) * 264 + col] =
                make_float2(qn1 + pn0 - 2.0f * a.z, qn1 + pn1 - 2.0f * a.w);
        }
    }
    __syncthreads();

    // ---- loo: warp w -> rows w*8..w*8+7; class = 2qb + (w>>3) ----
    const int cls = 2 * qb + (wid >> 3);
    const float* D = d2s + (size_t)(wid * 8) * 264 + lane * 8;
    float d2v[8][8];
#pragma unroll
    for (int r = 0; r < 8; r++){
        const float4 v0 = *(const float4*)(D + r * 264);
        const float4 v1 = *(const float4*)(D + r * 264 + 4);
        d2v[r][0] = v0.x; d2v[r][1] = v0.y; d2v[r][2] = v0.z; d2v[r][3] = v0.w;
        d2v[r][4] = v1.x; d2v[r][5] = v1.y; d2v[r][6] = v1.z; d2v[r][7] = v1.w;
    }

    float sacc[8];
#pragma unroll
    for (int j = 0; j < 8; j++) sacc[j] = 0.0f;
    float sumA2 = 0.0f;
    float cnt   = 0.0f;

#pragma unroll
    for (int r = 0; r < 8; r++){
        float ss = 0.0f;
        float mv = 3.4e38f;
        int   mi = 1 << 30;
#pragma unroll
        for (int j = 0; j < 8; j++){
            const int   p = lane * 8 + j;
            const float v = d2v[r][j];
            if (v < mv){ mv = v; mi = p; }        // ascending -> first min
            if (p != cls) ss = fmaf(v, v, ss);
        }
#pragma unroll
        for (int off = 16; off; off >>= 1){
            ss += __shfl_xor_sync(0xffffffffu, ss, off);
            const float ov = __shfl_xor_sync(0xffffffffu, mv, off);
            const int   oi = __shfl_xor_sync(0xffffffffu, mi, off);
            if (ov < mv || (ov == mv && oi < mi)){ mv = ov; mi = oi; }
        }
        const float inv = 1.0f / fmaxf(sqrtf(ss), EPSF);
#pragma unroll
        for (int j = 0; j < 8; j++){
            const int p = lane * 8 + j;
            if (p != cls) sacc[j] = fmaf(d2v[r][j], inv, sacc[j]);
        }
        if (lane == 0){
            sumA2 += ss * inv * inv;
            if (mi == cls) cnt += 1.0f;
        }
    }

#pragma unroll
    for (int j = 0; j < 8; j++) s_part[wid][lane * 8 + j] = sacc[j];
    if (lane == 0){
        atomicAdd(&s_scal[(wid >> 3) * 2],     sumA2);
        atomicAdd(&s_scal[(wid >> 3) * 2 + 1], cnt);
    }
    __syncthreads();

    // ||sum_q a_q||^2 per class: threads 0-255 -> class0, 256-511 -> class1
    {
        const int half = tid >> 8;
        const int cc   = tid & 255;
        float col = 0.0f;
#pragma unroll
        for (int w2 = 0; w2 < 8; w2++) col += s_part[half * 8 + w2][cc];
        float sq = col * col;
#pragma unroll
        for (int off = 16; off; off >>= 1) sq += __shfl_xor_sync(0xffffffffu, sq, off);
        if (lane == 0) s_red[wid] = sq;
    }
    __syncthreads();
    if (tid == 0){
        float S20 = 0.0f, S21 = 0.0f;
#pragma unroll
        for (int i = 0; i < 8; i++){ S20 += s_red[i]; S21 += s_red[8 + i]; }
        atomicAdd(&g_cos_sum, 0.5f * ((S20 - s_scal[0]) + (S21 - s_scal[2])));
        atomicAdd(&g_acc_cnt, s_scal[1] + s_scal[3]);
    }
}

// ---------------- K4: finalize -------------------------------------------
__global__ void k_final(float* __restrict__ out){
    if (threadIdx.x == 0){
        out[0] = g_cos_sum / (float)NPAIRS;
        out[1] = g_acc_cnt / (float)CQ;
    }
}

// ---------------- launch ---------------------------------------------------
extern "C" void kernel_launch(void* const* d_in, const int* in_sizes, int n_in,
                              void* d_out, int out_size){
    const float* xs = (const float*)d_in[0];
    const float* xq = (const float*)d_in[1];
    const float* W  = (const float*)d_in[2];
    float* out = (float*)d_out;
    (void)in_sizes; (void)n_in; (void)out_size;

    const int smem_gemm = 2 * G_BUF * (int)sizeof(float);       // ~66 KB
    const int smem_dloo = 128 * 264 * (int)sizeof(float);       // 135 KB (>= 2*D_BUF)
    cudaFuncSetAttribute(k_gemm, cudaFuncAttributeMaxDynamicSharedMemorySize, smem_gemm);
    cudaFuncSetAttribute(k_dloo, cudaFuncAttributeMaxDynamicSharedMemorySize, smem_dloo);

    k_wperm<<<32, 256>>>(W);
    k_gemm<<<M_TOT / 128, 512, smem_gemm>>>(xs, xq);
    k_proto<<<C_CLS, 128>>>();
    k_dloo<<<128, 512, smem_dloo>>>();
    k_final<<<1, 1>>>(out);
}